// round 10
// baseline (speedup 1.0000x reference)
#include <cuda_runtime.h>
#include <cuda_fp16.h>
#include <math.h>
#include <stdint.h>

#define CIN   64
#define COUT  128
#define HH    128
#define WW    128
#define NB    32

// ---------------- persistent scratch (__device__ globals) -------------------
// Activations: [n][h][pix(128)][ic(64)] fp16 (16KB per row tile)
__device__ uint4 g_x1[(size_t)NB * HH * 1024];
// Winograd-transformed weights: [pos(16)][oc(128)][ic(64)] fp16 (16KB per pos)
__device__ uint4 g_u[16 * 1024];

// ---------------- pre-pass: x -> fp16 transposed tiles ----------------------
__global__ void prep_x(const float* __restrict__ x) {
    __shared__ __half sh[128 * 72];
    const int h = blockIdx.x, n = blockIdx.y;
    const float* xb = x + (size_t)n * CIN * HH * WW;
#pragma unroll
    for (int i = 0; i < 8; i++) {
        int f = threadIdx.x + i * 256;      // 0..2047 = ic*32 + p4
        int ic = f >> 5, p4 = f & 31;
        float4 v = *(const float4*)(xb + ((size_t)ic * HH + h) * WW + p4 * 4);
        float vv[4] = {v.x, v.y, v.z, v.w};
#pragma unroll
        for (int j = 0; j < 4; j++)
            sh[(p4 * 4 + j) * 72 + ic] = __float2half_rn(vv[j]);
    }
    __syncthreads();
    uint4* dst = g_x1 + (size_t)(n * HH + h) * 1024;
    for (int q = threadIdx.x; q < 1024; q += 256) {
        int p = q >> 3, c = q & 7;
        dst[q] = *(const uint4*)((const char*)sh + p * 144 + c * 16);
    }
}

// ---------------- pre-pass: weights -> Winograd U, fp32-exact then fp16 -----
// g~[r][c] = w[ic][oc][2-r][2-c];  U = G g~ G^T,  G = [[1,0,0],[.5,.5,.5],
// [.5,-.5,.5],[0,0,1]].  Stored U[pos=pr*4+pc][oc][ic].
__global__ void prep_uw(const float* __restrict__ w) {
    int idx = blockIdx.x * 256 + threadIdx.x;      // 0..8191 = oc*64+ic
    if (idx >= COUT * CIN) return;
    int oc = idx >> 6, ic = idx & 63;
    float g[3][3];
#pragma unroll
    for (int r = 0; r < 3; r++)
#pragma unroll
        for (int c = 0; c < 3; c++)
            g[r][c] = w[((size_t)(ic * COUT + oc) * 3 + (2 - r)) * 3 + (2 - c)];
    float t[4][3];
#pragma unroll
    for (int c = 0; c < 3; c++) {
        t[0][c] = g[0][c];
        t[1][c] = 0.5f * (g[0][c] + g[1][c] + g[2][c]);
        t[2][c] = 0.5f * (g[0][c] - g[1][c] + g[2][c]);
        t[3][c] = g[2][c];
    }
    __half* dst = (__half*)g_u;
#pragma unroll
    for (int r = 0; r < 4; r++) {
        float u0 = t[r][0];
        float u1 = 0.5f * (t[r][0] + t[r][1] + t[r][2]);
        float u2 = 0.5f * (t[r][0] - t[r][1] + t[r][2]);
        float u3 = t[r][2];
        dst[((r * 4 + 0) * COUT + oc) * 64 + ic] = __float2half_rn(u0);
        dst[((r * 4 + 1) * COUT + oc) * 64 + ic] = __float2half_rn(u1);
        dst[((r * 4 + 2) * COUT + oc) * 64 + ic] = __float2half_rn(u2);
        dst[((r * 4 + 3) * COUT + oc) * 64 + ic] = __float2half_rn(u3);
    }
}

// ---------------- main kernel ----------------------------------------------
#define XSTG   0                       // x stage: 4 rows x 128 pix x 80B(pad)
#define XSTG_B 40960
#define VS     40960                   // V: 16 pos x 64 tiles x 144B(pad)
#define VPOS_B 9216
#define US     188416                  // U: 2 bufs x 128 oc x 144B(pad)
#define UT_B   18432
#define SMEM_SZ 225280

static __device__ __forceinline__ unsigned smem_u32(const void* p) {
    unsigned r;
    asm("{ .reg .u64 t; cvta.to.shared.u64 t, %1; cvt.u32.u64 %0, t; }"
        : "=r"(r) : "l"(p));
    return r;
}
__device__ __forceinline__ void cp16(unsigned dst, const void* src, int bytes) {
    asm volatile("cp.async.cg.shared.global [%0], [%1], 16, %2;"
                 :: "r"(dst), "l"(src), "r"(bytes));
}
__device__ __forceinline__ void cp_commit() {
    asm volatile("cp.async.commit_group;");
}
__device__ __forceinline__ void ldsm4(unsigned r[4], unsigned addr) {
    asm volatile("ldmatrix.sync.aligned.m8n8.x4.shared.b16 {%0,%1,%2,%3}, [%4];"
                 : "=r"(r[0]), "=r"(r[1]), "=r"(r[2]), "=r"(r[3]) : "r"(addr));
}
__device__ __forceinline__ void mma16816(float c[4], const unsigned a[4],
                                         unsigned b0, unsigned b1) {
    asm volatile(
        "mma.sync.aligned.m16n8k16.row.col.f32.f16.f16.f32 "
        "{%0,%1,%2,%3}, {%4,%5,%6,%7}, {%8,%9}, {%0,%1,%2,%3};"
        : "+f"(c[0]), "+f"(c[1]), "+f"(c[2]), "+f"(c[3])
        : "r"(a[0]), "r"(a[1]), "r"(a[2]), "r"(a[3]), "r"(b0), "r"(b1));
}
// gelu_tanh(y) == y * sigmoid(2*0.79788456*(y + 0.044715 y^3))
__device__ __forceinline__ float gelu_tanh(float y) {
    float u = 1.5957691216f * (y + 0.044715f * y * y * y);
    return __fdividef(y, 1.0f + __expf(-u));
}

extern __shared__ char dyn_smem[];

__global__ __launch_bounds__(256, 1)
void convt_wino_kernel(const float* __restrict__ bias,
                       const float* __restrict__ gnw,
                       const float* __restrict__ gnb,
                       float* __restrict__ out) {
    const int hb = blockIdx.x;          // output rows {2hb, 2hb+1}
    const int n = blockIdx.y;
    const int tid = threadIdx.x;
    const int wid = tid >> 5;
    const int l = tid & 31;

    const unsigned sb = smem_u32(dyn_smem);

    // ---- async load helpers ----
    auto issue_x = [&](int half) {
#pragma unroll
        for (int k = 0; k < 8; k++) {
            int idx = tid + k * 256;        // 0..2047
            int c = idx & 3, pix = (idx >> 2) & 127, i = idx >> 9;
            int gh = 2 * hb - 2 + i;
            const char* src = (const char*)g_x1 +
                (size_t)(n * HH + (gh < 0 ? 0 : gh)) * 16384 +
                pix * 128 + half * 64 + c * 16;
            cp16(sb + XSTG + (unsigned)(i * 128 + pix) * 80 + c * 16, src,
                 (gh >= 0) ? 16 : 0);
        }
        cp_commit();
    };
    auto issue_u = [&](int pos, int buf) {
#pragma unroll
        for (int k = 0; k < 4; k++) {
            int idx = tid + k * 256;        // 0..1023
            int c = idx & 7, oc = idx >> 3;
            cp16(sb + US + (unsigned)buf * UT_B + (unsigned)oc * 144 + c * 16,
                 (const char*)g_u + (size_t)pos * 16384 + oc * 128 + c * 16, 16);
        }
        cp_commit();
    };

    // ---- V transform for one ic-half (fp32 math, fp16 store) ----
    auto transform_half = [&](int half) {
#pragma unroll
        for (int jb = 0; jb < 4; jb++) {
            int idx = tid + jb * 256;       // 0..1023
            int t = idx >> 4, q = idx & 15; // q = ic-pair within half
            float2 d[4][4];
#pragma unroll
            for (int i = 0; i < 4; i++)
#pragma unroll
                for (int jj = 0; jj < 4; jj++) {
                    int pix = 2 * t - 2 + jj;
                    if (pix >= 0) {
                        __half2 hv = *(const __half2*)
                            (dyn_smem + (i * 128 + pix) * 80 + q * 4);
                        d[i][jj] = __half22float2(hv);
                    } else d[i][jj] = make_float2(0.f, 0.f);
                }
            float2 e[4][4];
#pragma unroll
            for (int jj = 0; jj < 4; jj++) {
                e[0][jj] = make_float2(d[0][jj].x - d[2][jj].x, d[0][jj].y - d[2][jj].y);
                e[1][jj] = make_float2(d[1][jj].x + d[2][jj].x, d[1][jj].y + d[2][jj].y);
                e[2][jj] = make_float2(d[2][jj].x - d[1][jj].x, d[2][jj].y - d[1][jj].y);
                e[3][jj] = make_float2(d[1][jj].x - d[3][jj].x, d[1][jj].y - d[3][jj].y);
            }
#pragma unroll
            for (int r = 0; r < 4; r++) {
                float2 v[4];
                v[0] = make_float2(e[r][0].x - e[r][2].x, e[r][0].y - e[r][2].y);
                v[1] = make_float2(e[r][1].x + e[r][2].x, e[r][1].y + e[r][2].y);
                v[2] = make_float2(e[r][2].x - e[r][1].x, e[r][2].y - e[r][1].y);
                v[3] = make_float2(e[r][1].x - e[r][3].x, e[r][1].y - e[r][3].y);
#pragma unroll
                for (int s = 0; s < 4; s++)
                    *(__half2*)(dyn_smem + VS + (r * 4 + s) * VPOS_B +
                                t * 144 + half * 64 + q * 4) =
                        __floats2half2_rn(v[s].x, v[s].y);
            }
        }
    };

    // ---- prologue: x half0 + U0, transforms, x half1 ----
    issue_x(0);                                  // g0
    issue_u(0, 0);                               // g1
    asm volatile("cp.async.wait_group 1;");      // g0 (xh0) done
    __syncthreads();
    transform_half(0);
    __syncthreads();                             // x stage reads done
    issue_x(1);                                  // g2
    asm volatile("cp.async.wait_group 0;");      // U0 + xh1 done
    __syncthreads();
    transform_half(1);
    __syncthreads();                             // V complete, U0 visible

    // ---- per-lane ldmatrix components (R9-proven patterns) ----
    const unsigned aRowK = (unsigned)((l & 15) * 144 + ((l >> 4) & 1) * 16);
    const int bRow = (l & 7) + ((l & 16) ? 8 : 0);
    const unsigned bKoff = (l & 8) ? 16u : 0u;

    // ---- Y accumulators: [patch pi][tn][creg][a*2+b] ----
    float Y[4][2][4][4];
#pragma unroll
    for (int pi = 0; pi < 4; pi++)
#pragma unroll
        for (int tn = 0; tn < 2; tn++)
#pragma unroll
            for (int c = 0; c < 4; c++)
#pragma unroll
                for (int ab = 0; ab < 4; ab++) Y[pi][tn][c][ab] = 0.f;

    constexpr float AR[2][4] = {{1.f, 1.f, 1.f, 0.f}, {0.f, 1.f, -1.f, -1.f}};

    // ---- mainloop over 16 Winograd positions ----
#pragma unroll
    for (int p = 0; p < 16; p++) {
        if (p > 0) {
            asm volatile("cp.async.wait_group 0;");   // U[p] done
            __syncthreads();                           // visible; U[p-1] consumed
        }
        if (p < 15) issue_u(p + 1, (p + 1) & 1);

        const int pr = p >> 2, pc = p & 3;
        const unsigned ub = sb + US + (unsigned)(p & 1) * UT_B +
                            (unsigned)(wid * 16) * 144;
        unsigned af[4][4];
#pragma unroll
        for (int kc = 0; kc < 4; kc++) ldsm4(af[kc], ub + aRowK + kc * 32);

#pragma unroll
        for (int pi = 0; pi < 4; pi++) {
            float tmp[2][4] = {{0.f, 0.f, 0.f, 0.f}, {0.f, 0.f, 0.f, 0.f}};
            const unsigned vb = sb + VS + (unsigned)p * VPOS_B +
                                (unsigned)((pi * 16 + bRow) * 144) + bKoff;
#pragma unroll
            for (int kc = 0; kc < 4; kc++) {
                unsigned bf[4];
                ldsm4(bf, vb + kc * 32);
                mma16816(tmp[0], af[kc], bf[0], bf[1]);
                mma16816(tmp[1], af[kc], bf[2], bf[3]);
            }
            // fold inverse transform (coefs 0/+-1, compile-time)
#pragma unroll
            for (int tn = 0; tn < 2; tn++)
#pragma unroll
                for (int c = 0; c < 4; c++) {
                    float m = tmp[tn][c];
#pragma unroll
                    for (int a = 0; a < 2; a++) {
                        if (AR[a][pr] == 0.f) continue;
#pragma unroll
                        for (int b = 0; b < 2; b++) {
                            if (AR[b][pc] == 0.f) continue;
                            Y[pi][tn][c][a * 2 + b] += AR[a][pr] * AR[b][pc] * m;
                        }
                    }
                }
        }
    }

    // ---------------- epilogue: bias + GELU + per-pixel GN + store ----------
    const int ocr = wid * 16 + (l >> 2);            // cregs 0,1; +8 for 2,3
    const float b_lo = __ldg(bias + ocr), b_hi = __ldg(bias + ocr + 8);
    const float w_lo = __ldg(gnw + ocr),  w_hi = __ldg(gnw + ocr + 8);
    const float a_lo = __ldg(gnb + ocr),  a_hi = __ldg(gnb + ocr + 8);

#pragma unroll
    for (int pi = 0; pi < 4; pi++) {
#pragma unroll
        for (int tn = 0; tn < 2; tn++) {
            float g[4][4], o[4][4];
#pragma unroll
            for (int ab = 0; ab < 4; ab++) {
                g[0][ab] = gelu_tanh(Y[pi][tn][0][ab] + b_lo);
                g[1][ab] = gelu_tanh(Y[pi][tn][1][ab] + b_lo);
                g[2][ab] = gelu_tanh(Y[pi][tn][2][ab] + b_hi);
                g[3][ab] = gelu_tanh(Y[pi][tn][3][ab] + b_hi);
            }
            // GN: group = this warp's 16 oc; pixel = (a, tile, b).
            // u=0 -> cregs {0,2} (tile t_a); u=1 -> cregs {1,3} (t_b)
#pragma unroll
            for (int u = 0; u < 2; u++)
#pragma unroll
                for (int ab = 0; ab < 4; ab++) {
                    float v0 = g[u][ab], v1 = g[u + 2][ab];
                    float s1 = v0 + v1, s2 = v0 * v0 + v1 * v1;
#pragma unroll
                    for (int m = 4; m <= 16; m <<= 1) {
                        s1 += __shfl_xor_sync(0xffffffffu, s1, m);
                        s2 += __shfl_xor_sync(0xffffffffu, s2, m);
                    }
                    float mean = s1 * (1.0f / 16.0f);
                    float var  = s2 * (1.0f / 16.0f) - mean * mean;
                    float rstd = rsqrtf(var + 1e-5f);
                    o[u][ab]     = (v0 - mean) * rstd * w_lo + a_lo;
                    o[u + 2][ab] = (v1 - mean) * rstd * w_hi + a_hi;
                }
            // stores: cols = 32*pi + 16*tn + 4*(l&3) + {0..3}
            int colbase = 32 * pi + 16 * tn + 4 * (l & 3);
#pragma unroll
            for (int rr = 0; rr < 2; rr++) {        // rr0 -> ocr, rr1 -> ocr+8
                int oc = ocr + rr * 8;
#pragma unroll
                for (int a = 0; a < 2; a++) {
                    float* dst = out + (((size_t)n * COUT + oc) * HH +
                                        (2 * hb + a)) * WW + colbase;
                    *(float4*)dst = make_float4(o[rr * 2 + 0][a * 2 + 0],
                                                o[rr * 2 + 0][a * 2 + 1],
                                                o[rr * 2 + 1][a * 2 + 0],
                                                o[rr * 2 + 1][a * 2 + 1]);
                }
            }
        }
    }
}

extern "C" void kernel_launch(void* const* d_in, const int* in_sizes, int n_in,
                              void* d_out, int out_size) {
    const float* x   = (const float*)d_in[0];
    const float* w   = (const float*)d_in[1];
    const float* b   = (const float*)d_in[2];
    const float* gnw = (const float*)d_in[3];
    const float* gnb = (const float*)d_in[4];
    float* out = (float*)d_out;

    prep_uw<<<32, 256>>>(w);
    prep_x<<<dim3(HH, NB), 256>>>(x);

    cudaFuncSetAttribute(convt_wino_kernel,
                         cudaFuncAttributeMaxDynamicSharedMemorySize, SMEM_SZ);
    convt_wino_kernel<<<dim3(HH / 2, NB), 256, SMEM_SZ>>>(b, gnw, gnb, out);
}